// round 1
// baseline (speedup 1.0000x reference)
#include <cuda_runtime.h>
#include <math.h>

// Problem constants: mask [8, 256, 256] float32
constexpr int B_ = 8;
constexpr int H_ = 256;
constexpr int W_ = 256;
constexpr int NT = B_ * H_ * W_;
constexpr float INF_F  = 1e10f;
constexpr float THR    = 0.5f;
constexpr float SCALE_F = 50.0f;

// Scratch (static device globals — no allocation allowed)
__device__ float g_tmp[NT];    // pass-1 result: min over xq of (x-xq)^2 + m
__device__ float g_dist[NT];   // pass-2 result: sqrt(d2)
__device__ unsigned int g_maxbits;  // global max distance (float bits, nonneg)

__global__ void k_reset() { g_maxbits = 0u; }

// Pass 1: per row (b,y): tmp[x] = min_xq ( (x-xq)^2 + m[xq] ),
// m = 0 where mask > THR else INF.
__global__ __launch_bounds__(256) void k_pass1(const float* __restrict__ mask) {
    const int row = blockIdx.x;          // b*H + y
    const int x = threadIdx.x;
    __shared__ float m[W_];
    m[x] = (mask[row * W_ + x] > THR) ? 0.0f : INF_F;
    __syncthreads();

    const float xf = (float)x;
    float best = 3.4e38f;
    #pragma unroll 16
    for (int xq = 0; xq < W_; ++xq) {
        const float d = xf - (float)xq;
        best = fminf(best, fmaf(d, d, m[xq]));   // broadcast shared read
    }
    g_tmp[row * W_ + x] = best;
}

// Pass 2: per (b, 8-wide x tile): d2[y,x] = min_yq ( (y-yq)^2 + tmp[yq,x] )
// 8-way register blocking over y per thread; fused sqrt + global max.
constexpr int XT = 8;                      // x-tile width
constexpr int P2_BLOCKS = B_ * (W_ / XT);  // 256 blocks

__global__ __launch_bounds__(256) void k_pass2() {
    const int b  = blockIdx.x / (W_ / XT);
    const int x0 = (blockIdx.x % (W_ / XT)) * XT;
    const int t  = threadIdx.x;

    __shared__ float tile[H_ * XT];        // 8 KB: tmp column slab [H][XT]
    const float* src = g_tmp + b * H_ * W_ + x0;
    #pragma unroll
    for (int j = 0; j < (H_ * XT) / 256; ++j) {
        const int idx = j * 256 + t;
        const int y  = idx / XT;
        const int xx = idx % XT;
        tile[idx] = src[y * W_ + xx];
    }
    __syncthreads();

    const int xx = t % XT;                 // column within tile
    const int y0 = (t / XT) * XT;          // 32 groups * 8 rows = 256 rows
    float best[XT];
    #pragma unroll
    for (int k = 0; k < XT; ++k) best[k] = 3.4e38f;

    const float y0f = (float)y0;
    for (int yq = 0; yq < H_; ++yq) {
        const float v  = tile[yq * XT + xx];   // broadcast within bank groups
        const float dd = y0f - (float)yq;
        #pragma unroll
        for (int k = 0; k < XT; ++k) {
            const float d = dd + (float)k;
            best[k] = fminf(best[k], fmaf(d, d, v));
        }
    }

    float* dst = g_dist + b * H_ * W_ + x0;
    float lmax = 0.0f;
    #pragma unroll
    for (int k = 0; k < XT; ++k) {
        const float dval = sqrtf(best[k]);
        lmax = fmaxf(lmax, dval);
        dst[(y0 + k) * W_ + xx] = dval;
    }

    // warp-level max reduce, one atomic per warp (float bits, nonneg -> uint order ok)
    #pragma unroll
    for (int off = 16; off; off >>= 1)
        lmax = fmaxf(lmax, __shfl_xor_sync(0xffffffffu, lmax, off));
    if ((t & 31) == 0)
        atomicMax(&g_maxbits, __float_as_uint(lmax));
}

// Final: out = 2 * sigmoid(-d / (max+1) * 50) = 2 / (1 + exp(d * 50/(max+1)))
__global__ __launch_bounds__(256) void k_final(float* __restrict__ out) {
    const int i = blockIdx.x * 256 + threadIdx.x;
    const float md = __uint_as_float(g_maxbits) + 1.0f;
    const float s  = SCALE_F / md;
    const float d  = g_dist[i];
    out[i] = 2.0f / (1.0f + expf(d * s));
}

extern "C" void kernel_launch(void* const* d_in, const int* in_sizes, int n_in,
                              void* d_out, int out_size) {
    const float* mask = (const float*)d_in[0];
    float* out = (float*)d_out;

    k_reset<<<1, 1>>>();
    k_pass1<<<B_ * H_, 256>>>(mask);
    k_pass2<<<P2_BLOCKS, 256>>>();
    k_final<<<NT / 256, 256>>>(out);
}

// round 3
// speedup vs baseline: 2.8939x; 2.8939x over previous
#include <cuda_runtime.h>
#include <math.h>

// Problem: mask [8,256,256] fp32. EDT (separable squared) -> normalize -> sigmoid.
constexpr int B_ = 8;
constexpr int H_ = 256;
constexpr int W_ = 256;
constexpr int NT = B_ * H_ * W_;
constexpr int NWORDS = W_ / 32;          // 8 bitmap words per row
constexpr float THR = 0.5f;
constexpr float INF_F = 1e10f;
constexpr float SCALE_F = 50.0f;

// Scratch (static device globals — no allocation allowed)
__device__ unsigned g_bits[B_ * NWORDS * H_]; // layout [b][wi][y] for coalesced col loads
__device__ float g_d2[NT];                    // squared distances
__device__ unsigned g_maxbits;                // max d2 as float bits (nonneg)

// ---------------------------------------------------------------------------
// Kernel 1: threshold mask into per-row bitmaps via ballot. Also reset max.
// grid = B*H blocks (one per row), 256 threads (one per x).
__global__ __launch_bounds__(256) void k_bits(const float* __restrict__ mask) {
    const int row = blockIdx.x;              // b*H + y
    const int x = threadIdx.x;
    const bool fg = mask[row * W_ + x] > THR;
    const unsigned bal = __ballot_sync(0xffffffffu, fg);
    if ((x & 31) == 0) {
        const int b = row >> 8;              // H_ == 256
        const int y = row & (H_ - 1);
        const int wi = x >> 5;
        g_bits[(b * NWORDS + wi) * H_ + y] = bal;
    }
    if (row == 0 && x == 0) g_maxbits = 0u;
}

// ---------------------------------------------------------------------------
// Kernel 2: fused pass1 (bit-scan nearest fg in row) + pass2 (outward min-plus
// scan over y with early exit). One block per (b, x) column; thread = y.
__global__ __launch_bounds__(256) void k_main() {
    const int b = blockIdx.x >> 8;           // blocks = b*W + x
    const int x = blockIdx.x & (W_ - 1);
    const int y = threadIdx.x;

    __shared__ unsigned bs[NWORDS * H_];     // [wi][y] — conflict-free for lane=y
    __shared__ float tmp_s[H_];

    #pragma unroll
    for (int wi = 0; wi < NWORDS; ++wi)
        bs[wi * H_ + y] = g_bits[(b * NWORDS + wi) * H_ + y];
    __syncthreads();

    // --- pass 1: nearest set bit to x in row y's bitmap ---
    const int wx = x >> 5;
    const int lx = x & 31;
    const unsigned wcur = bs[wx * H_ + y];
    int dl = 1 << 29, dr = 1 << 29;

    unsigned m = wcur & (0xFFFFFFFFu >> (31 - lx));              // bits <= x
    if (m) {
        dl = x - (wx * 32 + 31 - __clz((int)m));
    } else {
        for (int wi = wx - 1; wi >= 0; --wi) {
            const unsigned w = bs[wi * H_ + y];
            if (w) { dl = x - (wi * 32 + 31 - __clz((int)w)); break; }
        }
    }
    m = wcur & (0xFFFFFFFFu << lx);                              // bits >= x
    if (m) {
        dr = (wx * 32 + (__ffs((int)m) - 1)) - x;
    } else {
        for (int wi = wx + 1; wi < NWORDS; ++wi) {
            const unsigned w = bs[wi * H_ + y];
            if (w) { dr = (wi * 32 + (__ffs((int)w) - 1)) - x; break; }
        }
    }
    const int d = min(dl, dr);
    const float t = (d < (1 << 28)) ? (float)(d * d) : INF_F;    // exact: d<=255
    tmp_s[y] = t;
    __syncthreads();

    // --- pass 2: d2[y] = min_yq ( (y-yq)^2 + tmp[yq] ), outward scan w/ prune ---
    float best = t;                                              // yq == y term
    for (int k = 1; k < H_; ++k) {
        const float kk = (float)(k * k);
        if (kk >= best) break;                                   // exact prune (tmp>=0)
        const int ym = y - k, yp = y + k;
        if (ym >= 0)  best = fminf(best, kk + tmp_s[ym]);
        if (yp < H_)  best = fminf(best, kk + tmp_s[yp]);
    }

    g_d2[(b * H_ + y) * W_ + x] = best;

    // --- block max of d2, one atomic per block ---
    float lmax = best;
    #pragma unroll
    for (int off = 16; off; off >>= 1)
        lmax = fmaxf(lmax, __shfl_xor_sync(0xffffffffu, lmax, off));
    __shared__ float wmax[8];
    if ((y & 31) == 0) wmax[y >> 5] = lmax;
    __syncthreads();
    if (y == 0) {
        float bm = wmax[0];
        #pragma unroll
        for (int i = 1; i < 8; ++i) bm = fmaxf(bm, wmax[i]);
        atomicMax(&g_maxbits, __float_as_uint(bm));
    }
}

// ---------------------------------------------------------------------------
// Kernel 3: out = 2 / (1 + exp(sqrt(d2) * 50 / (sqrt(max_d2)+1))), float4.
__global__ __launch_bounds__(256) void k_final(float* __restrict__ out) {
    const int i = blockIdx.x * 256 + threadIdx.x;
    const float md = sqrtf(__uint_as_float(g_maxbits)) + 1.0f;   // == max(dist)+1 (monotone sqrt)
    const float s = SCALE_F / md;
    const float4 d2 = reinterpret_cast<const float4*>(g_d2)[i];
    float4 o;
    o.x = 2.0f / (1.0f + __expf(sqrtf(d2.x) * s));
    o.y = 2.0f / (1.0f + __expf(sqrtf(d2.y) * s));
    o.z = 2.0f / (1.0f + __expf(sqrtf(d2.z) * s));
    o.w = 2.0f / (1.0f + __expf(sqrtf(d2.w) * s));
    reinterpret_cast<float4*>(out)[i] = o;
}

// ---------------------------------------------------------------------------
extern "C" void kernel_launch(void* const* d_in, const int* in_sizes, int n_in,
                              void* d_out, int out_size) {
    const float* mask = (const float*)d_in[0];
    float* out = (float*)d_out;

    k_bits<<<B_ * H_, 256>>>(mask);
    k_main<<<B_ * W_, 256>>>();
    k_final<<<NT / 4 / 256, 256>>>(out);
}

// round 4
// speedup vs baseline: 3.1814x; 1.0994x over previous
#include <cuda_runtime.h>
#include <math.h>

// Problem: mask [8,256,256] fp32. EDT (separable squared) -> normalize -> sigmoid.
// Single-kernel design: phase1 (bitmaps) -> grid barrier -> phase2 (EDT via
// bit-scan + pruned outward min-plus, d2 kept in smem) -> grid barrier ->
// phase3 (sigmoid epilogue). Grid sized for guaranteed co-residency.
constexpr int B_ = 8;
constexpr int H_ = 256;
constexpr int W_ = 256;
constexpr float THR   = 0.5f;
constexpr float INF_F = 1e10f;

constexpr int NBLK = 256;              // 8 images * 32 column-tiles
constexpr int NTHR = 256;
constexpr int CPB  = 8;                // columns per block

// Scratch (static device globals; zero-initialized at module load)
__device__ unsigned g_bits[B_ * H_ * (W_ / 32)];   // [b][y][wi]
__device__ unsigned g_max;                          // max d2 (float bits, nonneg)
__device__ unsigned g_cnt0, g_cnt1, g_cnt2;         // barrier counters

__global__ __launch_bounds__(NTHR) void k_all(const float* __restrict__ mask,
                                              float* __restrict__ out) {
    const int blk  = blockIdx.x;
    const int t    = threadIdx.x;
    const int lane = t & 31;
    const int warp = t >> 5;

    __shared__ unsigned        bs[H_ * 8];          // 8KB: one image's bitmaps
    __shared__ unsigned short  tmp[H_ * CPB];       // 4KB: pass-1 distances
    __shared__ float           d2s[H_ * CPB];       // 8KB: squared distances
    __shared__ float           red[8];
    __shared__ float           s_scale;

    // ---- Phase 1: build bitmaps, 8 global rows per block (row = blk*8+warp)
    {
        const int row = blk * 8 + warp;            // 0..2047 == b*H + y
        #pragma unroll
        for (int j = 0; j < 8; ++j) {
            const float v = mask[row * W_ + j * 32 + lane];
            const unsigned bal = __ballot_sync(0xffffffffu, v > THR);
            if (lane == 0) g_bits[row * 8 + j] = bal;
        }
    }
    __threadfence();
    __syncthreads();
    if (t == 0) {
        atomicAdd(&g_cnt0, 1u);
        while (*((volatile unsigned*)&g_cnt0) < (unsigned)NBLK) __nanosleep(32);
    }
    __syncthreads();

    // ---- Phase 2: EDT for this block's 8 columns of image b
    const int b  = blk >> 5;
    const int x0 = (blk & 31) * CPB;

    #pragma unroll
    for (int j = 0; j < 8; ++j)                     // 8KB bitmap, L1-bypass
        bs[j * 256 + t] = __ldcg(&g_bits[b * 2048 + j * 256 + t]);
    __syncthreads();

    const int c  = t & 7;                           // column within tile
    const int x  = x0 + c;
    const int y0 = t >> 3;                          // 0..31
    const int wx = x >> 5;
    const unsigned mLo = 0xFFFFFFFFu >> (31 - (x & 31));
    const unsigned mHi = 0xFFFFFFFFu << (x & 31);

    // pass 1: nearest set bit in row y's bitmap (50% density => ~no word loops)
    #pragma unroll
    for (int i = 0; i < 8; ++i) {
        const int y = y0 + i * 32;
        const unsigned* row = bs + y * 8;
        const unsigned wcur = row[wx];
        int dl = 1 << 29, dr = 1 << 29;
        unsigned m = wcur & mLo;                    // bits <= x
        if (m) {
            dl = x - (wx * 32 + 31 - __clz(m));
        } else {
            #pragma unroll 1
            for (int wi = wx - 1; wi >= 0; --wi) {
                const unsigned w = row[wi];
                if (w) { dl = x - (wi * 32 + 31 - __clz(w)); break; }
            }
        }
        m = wcur & mHi;                             // bits >= x
        if (m) {
            dr = wx * 32 + (__ffs(m) - 1) - x;
        } else {
            #pragma unroll 1
            for (int wi = wx + 1; wi < 8; ++wi) {
                const unsigned w = row[wi];
                if (w) { dr = wi * 32 + (__ffs(w) - 1) - x; break; }
            }
        }
        const int d = min(dl, dr);
        tmp[y * 8 + c] = (d <= 255) ? (unsigned short)d : (unsigned short)0xFFFF;
    }
    __syncthreads();

    // pass 2: d2 = min_k ( k^2 + tmp[y+-k]^2 ), exact prune at k^2 >= best
    float lmax = 0.0f;
    #pragma unroll
    for (int i = 0; i < 8; ++i) {
        const int y = y0 + i * 32;
        const int d0 = tmp[y * 8 + c];
        float best = (d0 == 0xFFFF) ? INF_F : (float)(d0 * d0);
        #pragma unroll 1
        for (int k = 1; k < H_; ++k) {
            const float kk = (float)(k * k);
            if (kk >= best) break;
            const int ym = y - k;
            if (ym >= 0) {
                const int dm = tmp[ym * 8 + c];
                best = fminf(best, kk + ((dm == 0xFFFF) ? INF_F : (float)(dm * dm)));
            }
            const int yp = y + k;
            if (yp < H_) {
                const int dp = tmp[yp * 8 + c];
                best = fminf(best, kk + ((dp == 0xFFFF) ? INF_F : (float)(dp * dp)));
            }
        }
        d2s[y * 8 + c] = best;
        lmax = fmaxf(lmax, best);
    }

    // block max -> global atomic -> barrier 2 -> scale
    #pragma unroll
    for (int off = 16; off; off >>= 1)
        lmax = fmaxf(lmax, __shfl_xor_sync(0xffffffffu, lmax, off));
    if (lane == 0) red[warp] = lmax;
    __syncthreads();
    if (t == 0) {
        float bm = red[0];
        #pragma unroll
        for (int i = 1; i < 8; ++i) bm = fmaxf(bm, red[i]);
        atomicMax(&g_max, __float_as_uint(bm));
        __threadfence();
        atomicAdd(&g_cnt1, 1u);
        while (*((volatile unsigned*)&g_cnt1) < (unsigned)NBLK) __nanosleep(32);
        s_scale = 50.0f / (sqrtf(__uint_as_float(*((volatile unsigned*)&g_max))) + 1.0f);
    }
    __syncthreads();
    const float s = s_scale;

    // ---- Phase 3: epilogue straight from smem d2
    float* obase = out + b * H_ * W_ + x0;
    #pragma unroll
    for (int i = 0; i < 8; ++i) {
        const int y = y0 + i * 32;
        const float d2v = d2s[y * 8 + c];
        obase[y * W_ + c] = 2.0f / (1.0f + __expf(sqrtf(d2v) * s));
    }

    // ---- Reset for next graph replay (last block only; nobody reads after)
    __syncthreads();
    if (t == 0) {
        const unsigned old = atomicAdd(&g_cnt2, 1u);
        if (old == (unsigned)(NBLK - 1)) {
            g_cnt0 = 0u; g_cnt1 = 0u; g_cnt2 = 0u; g_max = 0u;
        }
    }
}

extern "C" void kernel_launch(void* const* d_in, const int* in_sizes, int n_in,
                              void* d_out, int out_size) {
    const float* mask = (const float*)d_in[0];
    float* out = (float*)d_out;
    k_all<<<NBLK, NTHR>>>(mask, out);
}